// round 15
// baseline (speedup 1.0000x reference)
#include <cuda_runtime.h>
#include <cuda_fp16.h>
#include <cuda_bf16.h>

// Inputs (metadata order):
// 0: nbr_ids   [N]  int32
// 1: seg_ids   [N]  int32   (unused; degree = N/G)
// 2: batch_idx [G]  int32
// 3: pos_idx   [G]  int32
// 4: s_tem     [B]  int32
// 5: r_tem     [B]  int32
// 6: dt_flat   [G]  float32
// 7: ent_embeds [NUM_ENTS*D] float32
// 8: rel_embeds [NUM_RELS*D] float32
// Output: [ s_embed_seq (G*3D floats) | s_hist_dt_seq (G floats) ]

#define F16_CAP (16 * 1024 * 1024)
__device__ __align__(256) __half g_ent_f16[F16_CAP];

// 256-bit evict-FIRST load (legal shapes on sm_100a: .v8.b32 / .v4.b64).
// The fp32 table is read-once-dead each replay: evict it immediately so the
// fp16 table, ids, and index arrays stay L2-resident for the gather kernel.
static __device__ __forceinline__ void ldg_ef_v8(const unsigned* p,
                                                 unsigned* v /* [8] */)
{
    asm volatile("ld.global.nc.L2::evict_first.v8.b32 "
                 "{%0,%1,%2,%3,%4,%5,%6,%7}, [%8];"
                 : "=r"(v[0]), "=r"(v[1]), "=r"(v[2]), "=r"(v[3]),
                   "=r"(v[4]), "=r"(v[5]), "=r"(v[6]), "=r"(v[7])
                 : "l"(p));
}

// ---------------- fp32 -> fp16 table conversion ----------------
// 64 B read (2 x v8.b32 evict_first) -> 32 B write per thread.
// fp16 writes use default policy (write-allocate): they are the next
// kernel's hot read set and nothing competes to evict them anymore.
__global__ void __launch_bounds__(256)
convert_f16_kernel(const unsigned* __restrict__ src, int n16)
{
    int i = blockIdx.x * 256 + threadIdx.x;
    if (i >= n16) return;
    unsigned v[16];
    ldg_ef_v8(src + 16 * (size_t)i, v);
    ldg_ef_v8(src + 16 * (size_t)i + 8, v + 8);

    uint4 o0, o1;
    {
        __half2 h0 = __floats2half2_rn(__uint_as_float(v[0]), __uint_as_float(v[1]));
        __half2 h1 = __floats2half2_rn(__uint_as_float(v[2]), __uint_as_float(v[3]));
        __half2 h2 = __floats2half2_rn(__uint_as_float(v[4]), __uint_as_float(v[5]));
        __half2 h3 = __floats2half2_rn(__uint_as_float(v[6]), __uint_as_float(v[7]));
        o0.x = *reinterpret_cast<unsigned*>(&h0);
        o0.y = *reinterpret_cast<unsigned*>(&h1);
        o0.z = *reinterpret_cast<unsigned*>(&h2);
        o0.w = *reinterpret_cast<unsigned*>(&h3);
    }
    {
        __half2 h0 = __floats2half2_rn(__uint_as_float(v[8]),  __uint_as_float(v[9]));
        __half2 h1 = __floats2half2_rn(__uint_as_float(v[10]), __uint_as_float(v[11]));
        __half2 h2 = __floats2half2_rn(__uint_as_float(v[12]), __uint_as_float(v[13]));
        __half2 h3 = __floats2half2_rn(__uint_as_float(v[14]), __uint_as_float(v[15]));
        o1.x = *reinterpret_cast<unsigned*>(&h0);
        o1.y = *reinterpret_cast<unsigned*>(&h1);
        o1.z = *reinterpret_cast<unsigned*>(&h2);
        o1.w = *reinterpret_cast<unsigned*>(&h3);
    }
    uint4* dst = reinterpret_cast<uint4*>(g_ent_f16);
    dst[2 * i]     = o0;
    dst[2 * i + 1] = o1;
}

// ---------------- Fast path (byte-exact R7/R13): DEG==32, D==256 ------------
// 4 groups x 64 lanes per 256-thread CTA, grid G/4, uint2 (8 B) gathers,
// ids via intra-warp shfl, HADD2 dual-bank accumulation merged in fp32.
// subj/rel/dt fused here (priced at the L2-cap path). Measured 24.0 us.
__global__ void __launch_bounds__(256)
agg_f16_kernel(const int* __restrict__ nbr_ids,
               const int* __restrict__ batch_idx,
               const int* __restrict__ pos_idx,
               const int* __restrict__ s_tem,
               const int* __restrict__ r_tem,
               const float* __restrict__ dt_flat,
               const float4* __restrict__ ent,    // fp32, row stride 64 float4
               const float4* __restrict__ rel,    // fp32, row stride 64 float4
               float4* __restrict__ out_embed,    // row stride 192 float4
               float* __restrict__ out_dt,
               int S)
{
    const int tid  = threadIdx.x;
    const int grp  = tid >> 6;          // 0..3 group within block
    const int lane = tid & 31;          // lane within warp
    const int t    = tid & 63;          // dim-lane within group (owns 4 dims)
    const int g    = (blockIdx.x << 2) + grp;

    // both warps of the group load the same ids (same addresses -> L1 broadcast)
    const int my_id = __ldg(&nbr_ids[(g << 5) + lane]);

    const uint2* tab = reinterpret_cast<const uint2*>(g_ent_f16); // row = 64 uint2

    const __half2 hz = __half2half2(__ushort_as_half(0));
    __half2 a0 = hz, a1 = hz, b0 = hz, b1 = hz;   // even bank (a), odd bank (b)

#pragma unroll
    for (int j = 0; j < 32; j += 2) {
        int idA = __shfl_sync(0xffffffffu, my_id, j);
        int idB = __shfl_sync(0xffffffffu, my_id, j + 1);
        uint2 va = __ldg(&tab[(idA << 6) + t]);   // 8 B = 4 halves
        uint2 vb = __ldg(&tab[(idB << 6) + t]);
        a0 = __hadd2(a0, *reinterpret_cast<const __half2*>(&va.x));
        a1 = __hadd2(a1, *reinterpret_cast<const __half2*>(&va.y));
        b0 = __hadd2(b0, *reinterpret_cast<const __half2*>(&vb.x));
        b1 = __hadd2(b1, *reinterpret_cast<const __half2*>(&vb.y));
    }

    const float inv = 1.0f / 32.0f;
    float2 fa0 = __half22float2(a0), fb0 = __half22float2(b0);
    float2 fa1 = __half22float2(a1), fb1 = __half22float2(b1);
    float4 m = make_float4((fa0.x + fb0.x) * inv, (fa0.y + fb0.y) * inv,
                           (fa1.x + fb1.x) * inv, (fa1.y + fb1.y) * inv);

    const int b = batch_idx[g];
    const int p = pos_idx[g];
    const int obase = (b * S + p) * 192;   // 3*256/4 float4 per output row

    float4 sv = __ldg(&ent[(s_tem[b] << 6) + t]);
    float4 rv = __ldg(&rel[(r_tem[b] << 6) + t]);

    // streaming stores: write-once output, evict-first
    __stcs(&out_embed[obase + t],       m);
    __stcs(&out_embed[obase + 64 + t],  sv);
    __stcs(&out_embed[obase + 128 + t], rv);

    if (t == 0) out_dt[b * S + p] = dt_flat[g];
}

// ---------------- Generic fallback: any DEG / D, fp32 ----------------
__global__ void agg_generic_kernel(const int* __restrict__ nbr_ids,
                                   const int* __restrict__ batch_idx,
                                   const int* __restrict__ pos_idx,
                                   const int* __restrict__ s_tem,
                                   const int* __restrict__ r_tem,
                                   const float* __restrict__ dt_flat,
                                   const float* __restrict__ ent,
                                   const float* __restrict__ rel,
                                   float* __restrict__ out_embed,
                                   float* __restrict__ out_dt,
                                   int S, int D, int DEG)
{
    const int g = blockIdx.x;
    const int b = batch_idx[g];
    const int p = pos_idx[g];
    const long obase = (long)(b * S + p) * (3L * D);
    const float inv = 1.0f / (float)DEG;

    for (int d = threadIdx.x; d < D; d += blockDim.x) {
        float sum = 0.f;
        for (int j = 0; j < DEG; ++j) {
            int id = nbr_ids[(long)g * DEG + j];
            sum += ent[(long)id * D + d];
        }
        out_embed[obase + d]         = sum * inv;
        out_embed[obase + D + d]     = ent[(long)s_tem[b] * D + d];
        out_embed[obase + 2 * D + d] = rel[(long)r_tem[b] * D + d];
    }
    if (threadIdx.x == 0) out_dt[b * S + p] = dt_flat[g];
}

extern "C" void kernel_launch(void* const* d_in, const int* in_sizes, int n_in,
                              void* d_out, int out_size)
{
    const int*   nbr_ids   = (const int*)  d_in[0];
    const int*   batch_idx = (const int*)  d_in[2];
    const int*   pos_idx   = (const int*)  d_in[3];
    const int*   s_tem     = (const int*)  d_in[4];
    const int*   r_tem     = (const int*)  d_in[5];
    const float* dt_flat   = (const float*)d_in[6];
    const float* ent       = (const float*)d_in[7];
    const float* rel       = (const float*)d_in[8];

    const int N    = in_sizes[0];
    const int G    = in_sizes[2];
    const int B    = in_sizes[4];
    const int ENTD = in_sizes[7];          // NUM_ENTS * D
    const int DEG  = N / G;
    const int S    = G / B;
    const int D    = ((out_size / G) - 1) / 3;

    float* out_embed = (float*)d_out;
    float* out_dt    = (float*)d_out + (long)G * 3L * D;

    if (DEG == 32 && D == 256 && (G & 3) == 0 && ENTD <= F16_CAP && (ENTD & 15) == 0) {
        const int n16 = ENTD >> 4;
        convert_f16_kernel<<<(n16 + 255) / 256, 256>>>((const unsigned*)ent, n16);
        agg_f16_kernel<<<G / 4, 256>>>(nbr_ids, batch_idx, pos_idx, s_tem, r_tem,
                                       dt_flat, (const float4*)ent, (const float4*)rel,
                                       (float4*)out_embed, out_dt, S);
    } else {
        agg_generic_kernel<<<G, 256>>>(nbr_ids, batch_idx, pos_idx, s_tem, r_tem,
                                       dt_flat, ent, rel, out_embed, out_dt,
                                       S, D, DEG);
    }
}